// round 9
// baseline (speedup 1.0000x reference)
#include <cuda_runtime.h>

#define Bq   16
#define Kq   32
#define Lq   1024
#define Dq   128
#define NEWL 48

// ---- scratch ----
__device__ int   g_order[Bq * Lq];          // l indices sorted by segment, per batch
__device__ int   g_off[Bq * (NEWL + 1)];
__device__ float g_tsum[Bq * NEWL];
__device__ int   g_done     = 0;            // prep completion counter (self-resetting)
__device__ int   g_consumed = 0;            // segmax gate-pass counter (self-resetting)

#define NEG_INF __int_as_float(0xff800000)
#define FMAX4(a, v) { a.x = fmaxf(a.x, v.x); a.y = fmaxf(a.y, v.y); \
                      a.z = fmaxf(a.z, v.z); a.w = fmaxf(a.w, v.w); }

#define N_SEG   3072u      // segmax blocks: 6 groups x 512 bk
#define N_ALM   24576u     // almat blocks: 6,291,456 float4 / 256

// ONE kernel. bid [0,16): prep. Remaining 27648 ids: every 9th is segmax (8:1
// almat:segmax interleave) so read-gather and write-stream share DRAM concurrently.
// NOTE: scratch produced in-launch (g_order/g_off/g_tsum) is read with PLAIN
// coherent loads — ld.global.nc (__ldg) may legally return stale data for
// locations written during the same launch, which broke R8.
__global__ void __launch_bounds__(256) mega_kernel(const float* __restrict__ h0,
                                                   const float* __restrict__ et,
                                                   const float* __restrict__ npm,
                                                   float* __restrict__ o_h,
                                                   float* __restrict__ o_pm,
                                                   float* __restrict__ o_et,
                                                   float* __restrict__ out_a) {
    const int t = threadIdx.x;
    const unsigned bid = blockIdx.x;

    if (bid < Bq) {
        // ================= prep: counting sort of l by segment, batch bid ======
        const int b = bid;
        __shared__ int   cnt[NEWL + 1];
        __shared__ int   off[NEWL + 1];
        __shared__ int   cur[NEWL + 1];
        __shared__ float ts[NEWL];

        if (t <= NEWL) { cnt[t] = 0; cur[t] = 0; }
        if (t < NEWL)  ts[t] = 0.f;
        __syncthreads();

        int ls[4], ss[4];
        #pragma unroll
        for (int r = 0; r < 4; ++r) {
            int   l  = r * 256 + t;
            float tv = __ldg(&et[b * Lq + l]);
            int   s  = (tv >= 0.f && tv < 48.f) ? (int)tv : NEWL;
            ls[r] = l; ss[r] = s;
            atomicAdd(&cnt[s], 1);
            if (s < NEWL) atomicAdd(&ts[s], tv);
        }
        __syncthreads();

        if (t <= NEWL) {                         // parallel exclusive prefix
            int a = 0;
            for (int i = 0; i < t; ++i) a += cnt[i];
            off[t] = a;
        }
        __syncthreads();

        #pragma unroll
        for (int r = 0; r < 4; ++r) {
            int pos = off[ss[r]] + atomicAdd(&cur[ss[r]], 1);
            g_order[b * Lq + pos] = ls[r];
        }
        if (t < NEWL)  g_tsum[b * NEWL + t] = ts[t];
        if (t <= NEWL) g_off[b * (NEWL + 1) + t] = off[t];

        __syncthreads();
        if (t == 0) { __threadfence(); atomicAdd(&g_done, 1); }   // release + signal
        return;
    }

    const unsigned b2 = bid - Bq;
    const unsigned q  = b2 / 9u;
    const unsigned r9 = b2 - q * 9u;

    if (r9 != 0) {
        // ================= almat: (B,K,L,48) one-hot float4 stores =============
        unsigned g   = (q * 8u + (r9 - 1u)) * 256u + t;   // float4 index, exact cover
        unsigned row = g / 12u;
        unsigned qq  = g - row * 12u;
        unsigned l   = row & (Lq - 1);
        unsigned b   = row >> 15;                 // / (K*L), K*L = 2^15
        float tv = __ldg(&et[b * Lq + l]);
        int s = (tv >= 0.f && tv < 48.f) ? (int)tv : NEWL;
        float4 v = make_float4(0.f, 0.f, 0.f, 0.f);
        int o = s - (int)(qq * 4u);
        if (o >= 0 && o < 4) (&v.x)[o] = 1.f;
        reinterpret_cast<float4*>(out_a)[g] = v;
        return;
    }

    // ================= segmax block q in [0, 3072) ============================
    // Gate on prep completion (atomic spin -> L2, always fresh); threadfence as
    // acquire; self-reset for graph replay (last of 3072 through the gate resets).
    if (t == 0) {
        while (atomicAdd(&g_done, 0) < Bq) __nanosleep(64);
        __threadfence();                          // acquire side of fence-fence sync
        int old = atomicAdd(&g_consumed, 1);
        if (old == (int)N_SEG - 1) {              // everyone has passed the gate
            atomicExch(&g_consumed, 0);
            atomicExch(&g_done, 0);
        }
    }
    __syncthreads();

    const int bk = (int)(q & 511u);               // 0..511
    const int b  = bk >> 5;                       // K = 32
    const int w  = t >> 5;                        // warp 0..7
    const int j  = t & 31;                        // lane
    const int s  = (int)(q >> 9) * 8 + w;         // segment: group (0..5)*8 + warp

    const int off = g_off[b * (NEWL + 1) + s];            // plain coherent loads
    const int cnt = g_off[b * (NEWL + 1) + s + 1] - off;
    const int* idx = g_order + b * Lq + off;

    const float4* base4 = reinterpret_cast<const float4*>(h0 + (size_t)bk * Lq * Dq) + j;
    float4 a0 = make_float4(NEG_INF, NEG_INF, NEG_INF, NEG_INF);
    float4 a1 = a0, a2 = a0, a3 = a0;
    int i = 0;
    for (; i + 4 <= cnt; i += 4) {
        int l0 = idx[i];     int l1 = idx[i + 1];
        int l2 = idx[i + 2]; int l3 = idx[i + 3];
        float4 v0 = base4[l0 * 32];
        float4 v1 = base4[l1 * 32];
        float4 v2 = base4[l2 * 32];
        float4 v3 = base4[l3 * 32];
        FMAX4(a0, v0); FMAX4(a1, v1); FMAX4(a2, v2); FMAX4(a3, v3);
    }
    for (; i < cnt; ++i) {
        float4 v = base4[idx[i] * 32];
        FMAX4(a0, v);
    }
    FMAX4(a0, a1); FMAX4(a2, a3); FMAX4(a0, a2);
    if (cnt < Lq) {                               // include_zero (empty: -inf -> 0)
        float4 z = make_float4(0.f, 0.f, 0.f, 0.f);
        FMAX4(a0, z);
    }
    reinterpret_cast<float4*>(o_h)[((size_t)bk * NEWL + s) * 32 + j] = a0;

    // msum (exact: 0/1 values), lane-strided gather + shuffle reduce
    const float* mrow = npm + (size_t)bk * Lq;
    float msum = 0.f;
    for (int i2 = j; i2 < cnt; i2 += 32) msum += __ldg(&mrow[idx[i2]]);
    #pragma unroll
    for (int d = 16; d > 0; d >>= 1) msum += __shfl_down_sync(0xffffffffu, msum, d);
    if (j == 0) {
        float denom = fmaxf((float)cnt, 1.f);
        o_pm[bk * NEWL + s] = msum / denom;
        o_et[bk * NEWL + s] = g_tsum[b * NEWL + s] / denom;
    }
}

extern "C" void kernel_launch(void* const* d_in, const int* in_sizes, int n_in,
                              void* d_out, int out_size) {
    const float* h0  = (const float*)d_in[0];
    const float* et  = (const float*)d_in[1];
    const float* npm = (const float*)d_in[2];
    float* out = (float*)d_out;

    float* o_h  = out;                              // (16,32,48,128) = 3,145,728
    float* o_et = out + 3145728;                    // (16,32,48)     =    24,576
    float* o_pm = out + 3145728 + 24576;            // (16,32,48)     =    24,576
    float* o_a  = out + 3145728 + 24576 + 24576;    // (16,32,1024,48)= 25,165,824

    mega_kernel<<<Bq + N_SEG + N_ALM, 256>>>(h0, et, npm, o_h, o_pm, o_et, o_a);
}